// round 1
// baseline (speedup 1.0000x reference)
#include <cuda_runtime.h>
#include <math.h>
#include <stdint.h>

// Problem constants
#define BB    512   // batch
#define STATE 256
#define DES   128   // command/desires dim
#define H     512   // hidden
#define NL    2

#define SPLITS 18
#define NCHUNK 129   // 128 d-chunks from hw_W + 1 chunk from hw_b (scale = 1)

// Scratch (device globals: no allocation allowed)
__device__ float g_buf0[BB * H];                 // embed output / layer input
__device__ float g_buf1[BB * H];                 // layer-0 output
__device__ float g_part[SPLITS][BB][H];          // split-K partials (~19 MB)

// ---------------------------------------------------------------------------
// Embed: out = tanh(state @ embed_w + embed_b)   [512,256]@[256,512]
// ---------------------------------------------------------------------------
__global__ void embed_kernel(const float* __restrict__ state,
                             const float* __restrict__ ew,
                             const float* __restrict__ eb) {
    int idx = blockIdx.x * blockDim.x + threadIdx.x;   // 0 .. 262143
    int b = idx >> 9;
    int j = idx & 511;
    float s = eb[j];
    const float* sp = state + b * STATE;
#pragma unroll 8
    for (int k = 0; k < STATE; k++)
        s = fmaf(sp[k], ew[k * H + j], s);
    g_buf0[idx] = tanhf(s);
}

// ---------------------------------------------------------------------------
// Split-K GEMM for one layer.
//   Virtual A[b, k] with k = d*512 + h :
//       d < 128 : A = cmd[b,d] * in[b,h],  B-row = hw_W[d*H*H + h*H + o]
//       d == 128: A = in[b,h],             B-row = hw_b[h*H + o]
//   Writes partial sums to g_part[split].
// CTA: 128x128 output tile, 256 threads, 8x8 per thread.
// Grid: (4 tiles_n, 4 tiles_m, SPLITS)
// ---------------------------------------------------------------------------
__global__ void __launch_bounds__(256, 2)
gemm_splitk(int layer,
            const float* __restrict__ cmd,
            const float* __restrict__ hwW,   // layer base: [128, 262144]
            const float* __restrict__ hwb)   // layer base: [262144]
{
    const float* inbuf = (layer == 0) ? g_buf0 : g_buf1;

    const int tn = blockIdx.x, tm = blockIdx.y, sp = blockIdx.z;
    const int m0 = tm * 128, n0 = tn * 128;

    // chunk range for this split: 129 = 18*7 + 3
    const int c_start = sp * 7 + (sp < 3 ? sp : 3);
    const int c_cnt   = 7 + (sp < 3 ? 1 : 0);

    __shared__ float sA[16][128];   // [k][m]  (transposed for frag loads)
    __shared__ float sB[16][128];   // [k][n]
    __shared__ float sScale[128];

    const int tid = threadIdx.x;
    const int tx = tid & 15;        // 0..15 -> n
    const int ty = tid >> 4;        // 0..15 -> m

    float acc[8][8];
#pragma unroll
    for (int i = 0; i < 8; i++)
#pragma unroll
        for (int j = 0; j < 8; j++) acc[i][j] = 0.0f;

    for (int ci = 0; ci < c_cnt; ci++) {
        const int d = c_start + ci;
        if (tid < 128)
            sScale[tid] = (d < DES) ? cmd[(m0 + tid) * DES + d] : 1.0f;
        const float* Bbase = (d < DES) ? (hwW + (size_t)d * (H * H)) : hwb;

        for (int kb = 0; kb < H; kb += 16) {
            __syncthreads();   // prev compute done; sScale visible
            // ---- load A tile: rows m0..m0+127, cols kb..kb+15 (scaled) ----
#pragma unroll
            for (int r = 0; r < 2; r++) {
                int g  = tid + r * 256;       // 0..511
                int m  = g & 127;
                int kq = g >> 7;              // 0..3
                float4 v = *(const float4*)&inbuf[(size_t)(m0 + m) * H + kb + kq * 4];
                float sc = sScale[m];
                sA[kq * 4 + 0][m] = v.x * sc;
                sA[kq * 4 + 1][m] = v.y * sc;
                sA[kq * 4 + 2][m] = v.z * sc;
                sA[kq * 4 + 3][m] = v.w * sc;
            }
            // ---- load B tile: 16 rows x 128 cols, coalesced ----
#pragma unroll
            for (int r = 0; r < 2; r++) {
                int g  = tid + r * 256;
                int n4 = g & 31;
                int k  = g >> 5;              // 0..15
                *(float4*)&sB[k][n4 * 4] =
                    *(const float4*)&Bbase[(size_t)(kb + k) * H + n0 + n4 * 4];
            }
            __syncthreads();
            // ---- compute 16 k-steps ----
#pragma unroll
            for (int k = 0; k < 16; k++) {
                float4 a0 = *(const float4*)&sA[k][ty * 8];
                float4 a1 = *(const float4*)&sA[k][ty * 8 + 4];
                float4 b0 = *(const float4*)&sB[k][tx * 8];
                float4 b1 = *(const float4*)&sB[k][tx * 8 + 4];
                float av[8] = {a0.x, a0.y, a0.z, a0.w, a1.x, a1.y, a1.z, a1.w};
                float bv[8] = {b0.x, b0.y, b0.z, b0.w, b1.x, b1.y, b1.z, b1.w};
#pragma unroll
                for (int i = 0; i < 8; i++)
#pragma unroll
                    for (int j = 0; j < 8; j++)
                        acc[i][j] = fmaf(av[i], bv[j], acc[i][j]);
            }
        }
    }

    // ---- write partials ----
    float* pp = &g_part[sp][0][0];
#pragma unroll
    for (int i = 0; i < 8; i++) {
        size_t row = (size_t)(m0 + ty * 8 + i) * H + n0 + tx * 8;
#pragma unroll
        for (int jq = 0; jq < 2; jq++) {
            float4 v = make_float4(acc[i][jq * 4 + 0], acc[i][jq * 4 + 1],
                                   acc[i][jq * 4 + 2], acc[i][jq * 4 + 3]);
            *(float4*)&pp[row + jq * 4] = v;
        }
    }
}

// ---------------------------------------------------------------------------
// Reduce split-K partials + small bias GEMM (c @ hb_W + hb_b) + ReLU.
// dst_is_buf1 != 0  -> write g_buf1 (layer-0 output), else write `dst` (d_out).
// ---------------------------------------------------------------------------
__global__ void reduce_bias_relu(const float* __restrict__ cmd,
                                 const float* __restrict__ hbW,  // [128,512]
                                 const float* __restrict__ hbb,  // [512]
                                 float* dst, int dst_is_buf1) {
    int idx = blockIdx.x * blockDim.x + threadIdx.x;   // 0..262143
    int b = idx >> 9;
    int o = idx & 511;
    float s = hbb[o];
#pragma unroll
    for (int sp = 0; sp < SPLITS; sp++) s += g_part[sp][b][o];
    const float* cp = cmd + b * DES;
#pragma unroll 8
    for (int k = 0; k < DES; k++)
        s = fmaf(cp[k], hbW[k * H + o], s);
    float r = fmaxf(s, 0.0f);
    if (dst_is_buf1) g_buf1[idx] = r;
    else             dst[idx] = r;
}

// ---------------------------------------------------------------------------
extern "C" void kernel_launch(void* const* d_in, const int* in_sizes, int n_in,
                              void* d_out, int out_size) {
    const float* state = (const float*)d_in[0];   // [512,256]
    const float* cmd   = (const float*)d_in[1];   // [512,128]
    const float* ew    = (const float*)d_in[2];   // [256,512]
    const float* eb    = (const float*)d_in[3];   // [512]
    const float* hwW   = (const float*)d_in[4];   // [2,128,262144]
    const float* hwb   = (const float*)d_in[5];   // [2,262144]
    const float* hbW   = (const float*)d_in[6];   // [2,128,512]
    const float* hbb   = (const float*)d_in[7];   // [2,512]
    float* out = (float*)d_out;                   // [512,512]

    const size_t HWW_L = (size_t)DES * H * H;     // 33,554,432
    const size_t HWB_L = (size_t)H * H;
    const size_t HBW_L = (size_t)DES * H;
    const size_t HBB_L = (size_t)H;

    embed_kernel<<<1024, 256>>>(state, ew, eb);

    dim3 grid(4, 4, SPLITS);

    // layer 0: input g_buf0 -> g_buf1
    gemm_splitk<<<grid, 256>>>(0, cmd, hwW + 0 * HWW_L, hwb + 0 * HWB_L);
    reduce_bias_relu<<<1024, 256>>>(cmd, hbW + 0 * HBW_L, hbb + 0 * HBB_L,
                                    out, /*dst_is_buf1=*/1);

    // layer 1: input g_buf1 -> d_out
    gemm_splitk<<<grid, 256>>>(1, cmd, hwW + 1 * HWW_L, hwb + 1 * HWB_L);
    reduce_bias_relu<<<1024, 256>>>(cmd, hbW + 1 * HBW_L, hbb + 1 * HBB_L,
                                    out, /*dst_is_buf1=*/0);
}

// round 3
// speedup vs baseline: 2.1851x; 2.1851x over previous
#include <cuda_runtime.h>
#include <cstdint>
#include <math.h>

#define BB    512
#define STATE 256
#define DES   128
#define H     512
#define SPLITS 18
#define PADW 136   // 136 mod 32 = 8 -> conflict-free fragment access

__device__ float g_buf0[BB * H];
__device__ float g_buf1[BB * H];
__device__ float g_part[SPLITS][BB][H];

__device__ __forceinline__ uint32_t f2tf32(float x) {
    uint32_t u; asm("cvt.rna.tf32.f32 %0, %1;" : "=r"(u) : "f"(x)); return u;
}
__device__ __forceinline__ void mma_m16n8k8(float* c, const uint32_t* a, const uint32_t* b) {
    asm volatile("mma.sync.aligned.m16n8k8.row.col.f32.tf32.tf32.f32 "
                 "{%0,%1,%2,%3}, {%4,%5,%6,%7}, {%8,%9}, {%0,%1,%2,%3};"
                 : "+f"(c[0]), "+f"(c[1]), "+f"(c[2]), "+f"(c[3])
                 : "r"(a[0]), "r"(a[1]), "r"(a[2]), "r"(a[3]), "r"(b[0]), "r"(b[1]));
}

// ---------------------------------------------------------------------------
// Embed: out = tanh(state @ embed_w + embed_b)
// ---------------------------------------------------------------------------
__global__ void embed_kernel(const float* __restrict__ state,
                             const float* __restrict__ ew,
                             const float* __restrict__ eb) {
    int idx = blockIdx.x * blockDim.x + threadIdx.x;
    int b = idx >> 9;
    int j = idx & 511;
    float s = eb[j];
    const float* sp = state + b * STATE;
#pragma unroll 8
    for (int k = 0; k < STATE; k++)
        s = fmaf(sp[k], ew[k * H + j], s);
    g_buf0[idx] = tanhf(s);
}

// ---------------------------------------------------------------------------
// tf32 mma.sync split-K GEMM.
//   virtual A[b, d*512+h] = cmd[b,d] * in[b,h]   (chunk d=128 -> hw_b, scale 1)
// CTA: 128x128 tile, 256 threads = 8 warps (2x4 grid of 64x32 warp tiles).
// ---------------------------------------------------------------------------
__global__ void __launch_bounds__(256, 2)
gemm_mma(int layer, const float* __restrict__ cmd,
         const float* __restrict__ hwW, const float* __restrict__ hwb)
{
    __shared__ __align__(16) uint32_t sA[16 * PADW];   // [k][m] tf32
    __shared__ __align__(16) uint32_t sB[16 * PADW];   // [k][n] tf32

    const int t    = threadIdx.x;
    const int lane = t & 31;
    const int w    = t >> 5;
    const int wm   = w & 1;      // 0..1 -> 64-row group
    const int wn   = w >> 1;     // 0..3 -> 32-col group

    const int n0 = blockIdx.x * 128;
    const int m0 = blockIdx.y * 128;
    const int sp = blockIdx.z;
    const int c0  = sp * 7 + (sp < 3 ? sp : 3);
    const int cnt = 7 + (sp < 3 ? 1 : 0);

    const float* __restrict__ inbuf = layer ? g_buf1 : g_buf0;

    const int am  = t & 127;          // A row this thread stages
    const int akq = t >> 7;           // 0/1 -> k-quad base
    const float* inrow = inbuf + (size_t)(m0 + am) * H;

    float acc[4][4][4];
#pragma unroll
    for (int i = 0; i < 4; i++)
#pragma unroll
        for (int j = 0; j < 4; j++)
#pragma unroll
            for (int q = 0; q < 4; q++) acc[i][j][q] = 0.0f;

    for (int ci = 0; ci < cnt; ci++) {
        const int d = c0 + ci;
        const float sc = (d < DES) ? cmd[(m0 + am) * DES + d] : 1.0f;
        const float* __restrict__ Bb = (d < DES) ? (hwW + (size_t)d * (H * H)) : hwb;

        for (int kb = 0; kb < H; kb += 16) {
            __syncthreads();
            // ---- stage A tile [16 x 128], scaled + tf32 ----
#pragma unroll
            for (int r = 0; r < 2; r++) {
                int kq = akq + 2 * r;                       // 0..3
                float4 v = *(const float4*)(inrow + kb + kq * 4);
                int base = (kq * 4) * PADW + am;
                sA[base]            = f2tf32(v.x * sc);
                sA[base + PADW]     = f2tf32(v.y * sc);
                sA[base + 2 * PADW] = f2tf32(v.z * sc);
                sA[base + 3 * PADW] = f2tf32(v.w * sc);
            }
            // ---- stage B tile [16 x 128], tf32 ----
#pragma unroll
            for (int r = 0; r < 2; r++) {
                int g  = t + r * 256;
                int n4 = g & 31;
                int k  = g >> 5;                            // 0..15
                float4 v = *(const float4*)&Bb[(size_t)(kb + k) * H + n0 + n4 * 4];
                uint32_t* p = &sB[k * PADW + n4 * 4];
                uint4 u = make_uint4(f2tf32(v.x), f2tf32(v.y), f2tf32(v.z), f2tf32(v.w));
                *(uint4*)p = u;
            }
            __syncthreads();
            // ---- 2 x k8 MMA steps ----
#pragma unroll
            for (int k8 = 0; k8 < 16; k8 += 8) {
                uint32_t a[4][4], b[4][2];
                const int kk = k8 + (lane & 3);
#pragma unroll
                for (int mi = 0; mi < 4; mi++) {
                    int row = wm * 64 + mi * 16 + (lane >> 2);
                    a[mi][0] = sA[kk * PADW + row];
                    a[mi][1] = sA[kk * PADW + row + 8];
                    a[mi][2] = sA[(kk + 4) * PADW + row];
                    a[mi][3] = sA[(kk + 4) * PADW + row + 8];
                }
#pragma unroll
                for (int ni = 0; ni < 4; ni++) {
                    int col = wn * 32 + ni * 8 + (lane >> 2);
                    b[ni][0] = sB[kk * PADW + col];
                    b[ni][1] = sB[(kk + 4) * PADW + col];
                }
#pragma unroll
                for (int mi = 0; mi < 4; mi++)
#pragma unroll
                    for (int ni = 0; ni < 4; ni++)
                        mma_m16n8k8(acc[mi][ni], a[mi], b[ni]);
            }
        }
    }

    // ---- epilogue: write partials (float2 per frag-half) ----
#pragma unroll
    for (int mi = 0; mi < 4; mi++) {
#pragma unroll
        for (int ni = 0; ni < 4; ni++) {
            int row = m0 + wm * 64 + mi * 16 + (lane >> 2);
            int col = n0 + wn * 32 + ni * 8 + (lane & 3) * 2;
            float2 v01 = make_float2(acc[mi][ni][0], acc[mi][ni][1]);
            float2 v23 = make_float2(acc[mi][ni][2], acc[mi][ni][3]);
            *(float2*)&g_part[sp][row][col]     = v01;
            *(float2*)&g_part[sp][row + 8][col] = v23;
        }
    }
}

// ---------------------------------------------------------------------------
// Reduce split-K partials + (c @ hb_W + hb_b) + ReLU.
// ---------------------------------------------------------------------------
__global__ void reduce_bias_relu(const float* __restrict__ cmd,
                                 const float* __restrict__ hbW,
                                 const float* __restrict__ hbb,
                                 float* dst, int dst_is_buf1) {
    int idx = blockIdx.x * blockDim.x + threadIdx.x;
    int b = idx >> 9;
    int o = idx & 511;
    float s = hbb[o];
#pragma unroll
    for (int sp = 0; sp < SPLITS; sp++) s += g_part[sp][b][o];
    const float* cp = cmd + b * DES;
#pragma unroll 16
    for (int k = 0; k < DES; k++)
        s = fmaf(cp[k], hbW[k * H + o], s);
    float r = fmaxf(s, 0.0f);
    if (dst_is_buf1) g_buf1[idx] = r;
    else             dst[idx] = r;
}

// ---------------------------------------------------------------------------
extern "C" void kernel_launch(void* const* d_in, const int* in_sizes, int n_in,
                              void* d_out, int out_size) {
    const float* state = (const float*)d_in[0];
    const float* cmd   = (const float*)d_in[1];
    const float* ew    = (const float*)d_in[2];
    const float* eb    = (const float*)d_in[3];
    const float* hwW   = (const float*)d_in[4];
    const float* hwb   = (const float*)d_in[5];
    const float* hbW   = (const float*)d_in[6];
    const float* hbb   = (const float*)d_in[7];
    float* out = (float*)d_out;

    const size_t HWW_L = (size_t)DES * H * H;
    const size_t HWB_L = (size_t)H * H;
    const size_t HBW_L = (size_t)DES * H;
    const size_t HBB_L = (size_t)H;

    embed_kernel<<<1024, 256>>>(state, ew, eb);

    dim3 grid(4, 4, SPLITS);

    gemm_mma<<<grid, 256>>>(0, cmd, hwW, hwb);
    reduce_bias_relu<<<1024, 256>>>(cmd, hbW, hbb, out, 1);

    gemm_mma<<<grid, 256>>>(1, cmd, hwW + HWW_L, hwb + HWB_L);
    reduce_bias_relu<<<1024, 256>>>(cmd, hbW + HBW_L, hbb + HBB_L, out, 0);
}